// round 15
// baseline (speedup 1.0000x reference)
#include <cuda_runtime.h>
#include <cuda_bf16.h>
#include <cstdint>

#define BB 8
#define LXX 2048
#define LYY 2048
#define DD 256

// ---------------- global scratch (no cudaMalloc allowed) ----------------
__device__ __nv_bfloat16 g_x_h[BB * LXX * DD];    // raw x, bf16 hi/lo
__device__ __nv_bfloat16 g_x_l[BB * LXX * DD];
__device__ __nv_bfloat16 g_xp_h[BB * LXX * DD];
__device__ __nv_bfloat16 g_xp_l[BB * LXX * DD];
__device__ __nv_bfloat16 g_yp_h[BB * LYY * DD];
__device__ __nv_bfloat16 g_yp_l[BB * LYY * DD];
__device__ __nv_bfloat16 g_yv_h[BB * LYY * DD];   // raw y, bf16 hi/lo
__device__ __nv_bfloat16 g_yv_l[BB * LYY * DD];
__device__ __nv_bfloat16 g_W_h[DD * DD];
__device__ __nv_bfloat16 g_W_l[DD * DD];

// ---------------- helpers (portable PTX only: sm_80-era) ----------------
__device__ __forceinline__ uint32_t smem_u32(const void* p) {
    uint32_t a;
    asm("{ .reg .u64 t; cvta.to.shared.u64 t, %1; cvt.u32.u64 %0, t; }" : "=r"(a) : "l"(p));
    return a;
}
__device__ __forceinline__ void cpa16(uint32_t s, const void* g) {
    asm volatile("cp.async.cg.shared.global [%0], [%1], 16;" :: "r"(s), "l"(g));
}
__device__ __forceinline__ void cpa4(uint32_t s, const void* g) {
    asm volatile("cp.async.ca.shared.global [%0], [%1], 4;" :: "r"(s), "l"(g));
}
#define CP_COMMIT() asm volatile("cp.async.commit_group;" ::: "memory")
#define CP_WAIT0()  asm volatile("cp.async.wait_group 0;" ::: "memory")
#define CP_WAIT1()  asm volatile("cp.async.wait_group 1;" ::: "memory")

__device__ __forceinline__ void ldsm4(uint32_t r[4], uint32_t a) {
    asm volatile("ldmatrix.sync.aligned.m8n8.x4.shared.b16 {%0,%1,%2,%3}, [%4];"
                 : "=r"(r[0]), "=r"(r[1]), "=r"(r[2]), "=r"(r[3]) : "r"(a));
}
__device__ __forceinline__ void ldsm4t(uint32_t r[4], uint32_t a) {
    asm volatile("ldmatrix.sync.aligned.m8n8.x4.trans.shared.b16 {%0,%1,%2,%3}, [%4];"
                 : "=r"(r[0]), "=r"(r[1]), "=r"(r[2]), "=r"(r[3]) : "r"(a));
}
__device__ __forceinline__ void mma16816(float c[4], const uint32_t a[4],
                                         uint32_t b0, uint32_t b1) {
    asm volatile(
        "mma.sync.aligned.m16n8k16.row.col.f32.bf16.bf16.f32 "
        "{%0,%1,%2,%3}, {%4,%5,%6,%7}, {%8,%9}, {%0,%1,%2,%3};"
        : "+f"(c[0]), "+f"(c[1]), "+f"(c[2]), "+f"(c[3])
        : "r"(a[0]), "r"(a[1]), "r"(a[2]), "r"(a[3]), "r"(b0), "r"(b1));
}
__device__ __forceinline__ uint32_t cvt2bf(float lo, float hi) {
    uint32_t r;
    asm("cvt.rn.bf16x2.f32 %0, %1, %2;" : "=r"(r) : "f"(hi), "f"(lo));
    return r;
}
// MUFU exp2 (ex2.approx): ~2 ulp, returns 0 for very negative inputs.
__device__ __forceinline__ float ex2a(float x) {
    float r;
    asm("ex2.approx.f32 %0, %1;" : "=f"(r) : "f"(x));
    return r;
}
#define L2E 1.4426950408889634f

// ---------------------------------------------------------------------------
// Fused elementwise bf16 hi/lo splitter: blocks [0,64) -> W, [64,4160) -> x,
// [4160,8256) -> y.
// ---------------------------------------------------------------------------
#define SPLIT_WBLK ((DD * DD) / 1024)              // 64
#define SPLIT_HALF ((BB * LXX * DD) / 1024)        // 4096
__global__ __launch_bounds__(256)
void split_all(const float* __restrict__ x, const float* __restrict__ y,
               const float* __restrict__ W)
{
    const int bidx = blockIdx.x;
    const float* src;
    __nv_bfloat16 *dh, *dl;
    size_t i;
    if (bidx < SPLIT_WBLK) {
        src = W; dh = g_W_h; dl = g_W_l;
        i = ((size_t)bidx * 256 + threadIdx.x) * 4;
    } else if (bidx < SPLIT_WBLK + SPLIT_HALF) {
        src = x; dh = g_x_h; dl = g_x_l;
        i = ((size_t)(bidx - SPLIT_WBLK) * 256 + threadIdx.x) * 4;
    } else {
        src = y; dh = g_yv_h; dl = g_yv_l;
        i = ((size_t)(bidx - SPLIT_WBLK - SPLIT_HALF) * 256 + threadIdx.x) * 4;
    }
    float4 v = *(const float4*)(src + i);
    float vv[4] = {v.x, v.y, v.z, v.w};
    __nv_bfloat16 h[4], l[4];
#pragma unroll
    for (int k = 0; k < 4; k++) {
        h[k] = __float2bfloat16_rn(vv[k]);
        l[k] = __float2bfloat16_rn(vv[k] - __bfloat162float(h[k]));
    }
    *(uint2*)&dh[i] = *(uint2*)h;
    *(uint2*)&dl[i] = *(uint2*)l;
}

// ---------------------------------------------------------------------------
// Tensor-core projection v2 (unchanged from R14): C = relu(A @ W^T + b).
// CTA = 128x128; A and W both streamed per k32 chunk, double-buffered;
// smem 80KB => 2 CTAs/SM. 3-pass hh+hl+lh; W frags register double-buffered.
// ---------------------------------------------------------------------------
#define PJ_AH 0
#define PJ_AL 10240
#define PJ_WH 20480
#define PJ_WL 30720
#define PJ_STG 40960
#define PJ_TOT (2 * PJ_STG)

__global__ __launch_bounds__(256, 2)
void proj_mma_kernel(const float* __restrict__ bias)
{
    extern __shared__ char smc[];
    const uint32_t sa = smem_u32(smc);
    const int tid  = threadIdx.x;
    const int w    = tid >> 5;
    const int lane = tid & 31;
    const int lr   = lane >> 2;
    const int tig  = lane & 3;
    const int rw   = w * 16;
    const int wcol0 = blockIdx.y * 128;
    const int row0  = blockIdx.x * 128;
    const bool isx  = row0 < BB * LXX;
    const int arow0 = isx ? row0 : row0 - BB * LXX;

    const __nv_bfloat16* __restrict__ Ah = isx ? g_x_h : g_yv_h;
    const __nv_bfloat16* __restrict__ Al = isx ? g_x_l : g_yv_l;
    __nv_bfloat16* __restrict__ Ch = isx ? g_xp_h : g_yp_h;
    __nv_bfloat16* __restrict__ Cl = isx ? g_xp_l : g_yp_l;

    const int pre_r = tid >> 1, pre_hb = tid & 1;

    auto pref = [&](int s, int kc) {
        const uint32_t st = sa + (uint32_t)(s * PJ_STG + pre_r * 80 + pre_hb * 32);
        const size_t ao = (size_t)(arow0 + pre_r) * DD + kc * 32 + pre_hb * 16;
        const size_t wo = (size_t)(wcol0 + pre_r) * DD + kc * 32 + pre_hb * 16;
        cpa16(st + PJ_AH,      Ah + ao);  cpa16(st + PJ_AH + 16,  Ah + ao + 8);
        cpa16(st + PJ_AL,      Al + ao);  cpa16(st + PJ_AL + 16,  Al + ao + 8);
        cpa16(st + PJ_WH,      g_W_h + wo); cpa16(st + PJ_WH + 16, g_W_h + wo + 8);
        cpa16(st + PJ_WL,      g_W_l + wo); cpa16(st + PJ_WL + 16, g_W_l + wo + 8);
    };
    pref(0, 0);
    CP_COMMIT();

    float O[16][4];
#pragma unroll
    for (int i = 0; i < 16; i++) { O[i][0] = O[i][1] = O[i][2] = O[i][3] = 0.f; }

    const uint32_t aAo = (uint32_t)(PJ_AH + (rw + (lane & 7) + ((lane >> 3) & 1) * 8) * 80
                        + (lane >> 4) * 16);
    const uint32_t aWo = (uint32_t)(PJ_WH + ((lane & 7) + ((lane < 16) ? 0 : 8)) * 80
                        + ((lane >> 3) & 1) * 16);

#pragma unroll 1
    for (int kc = 0; kc < 8; kc++) {
        const int s = kc & 1;
        if (kc < 7) { pref(s ^ 1, kc + 1); CP_COMMIT(); CP_WAIT1(); }
        else        { CP_WAIT0(); }
        __syncthreads();

        const uint32_t stb = sa + (uint32_t)(s * PJ_STG);
        const uint32_t aA  = stb + aAo;
        const uint32_t aAl = aA + (PJ_AL - PJ_AH);
        const uint32_t aW  = stb + aWo;
        const uint32_t aWl = aW + (PJ_WL - PJ_WH);
#pragma unroll
        for (int kk = 0; kk < 2; kk++) {
            uint32_t ah[4], al[4];
            ldsm4(ah, aA  + kk * 32);
            ldsm4(al, aAl + kk * 32);
            uint32_t wb[2][8];
            ldsm4(&wb[0][0], aW  + kk * 32);
            ldsm4(&wb[0][4], aWl + kk * 32);
#pragma unroll
            for (int g = 0; g < 8; g++) {
                const int cur = g & 1, nxt = cur ^ 1;
                if (g < 7) {
                    ldsm4(&wb[nxt][0], aW  + (g + 1) * 1280 + kk * 32);
                    ldsm4(&wb[nxt][4], aWl + (g + 1) * 1280 + kk * 32);
                }
                const uint32_t* bh = &wb[cur][0];
                const uint32_t* bl = &wb[cur][4];
                mma16816(O[2 * g],     ah, bh[0], bh[1]);
                mma16816(O[2 * g],     ah, bl[0], bl[1]);
                mma16816(O[2 * g],     al, bh[0], bh[1]);
                mma16816(O[2 * g + 1], ah, bh[2], bh[3]);
                mma16816(O[2 * g + 1], ah, bl[2], bl[3]);
                mma16816(O[2 * g + 1], al, bh[2], bh[3]);
            }
        }
        __syncthreads();
    }

    // ---- epilogue: bias + relu + h/l split + store ----
    const int r0g = arow0 + rw + lr;
#pragma unroll
    for (int f = 0; f < 16; f++) {
        int c = wcol0 + f * 8 + tig * 2;
        float b0 = __ldg(bias + c), b1 = __ldg(bias + c + 1);
        {
            float v0 = fmaxf(O[f][0] + b0, 0.f), v1 = fmaxf(O[f][1] + b1, 0.f);
            uint32_t h = cvt2bf(v0, v1);
            float q0 = v0 - __uint_as_float(h << 16);
            float q1 = v1 - __uint_as_float(h & 0xffff0000u);
            uint32_t l = cvt2bf(q0, q1);
            size_t o = (size_t)r0g * DD + c;
            *(uint32_t*)&Ch[o] = h;
            *(uint32_t*)&Cl[o] = l;
        }
        {
            float v0 = fmaxf(O[f][2] + b0, 0.f), v1 = fmaxf(O[f][3] + b1, 0.f);
            uint32_t h = cvt2bf(v0, v1);
            float q0 = v0 - __uint_as_float(h << 16);
            float q1 = v1 - __uint_as_float(h & 0xffff0000u);
            uint32_t l = cvt2bf(q0, q1);
            size_t o = (size_t)(r0g + 8) * DD + c;
            *(uint32_t*)&Ch[o] = h;
            *(uint32_t*)&Cl[o] = l;
        }
    }
}

// ---------------------------------------------------------------------------
// Fused mma.sync attention: 256 threads, XTILE 128, JTILE 32.
// S phase: 3-pass hh+hl+lh, register double-buffered frags. MUFU softmax.
// NEW (R15): yV(t) issued at top (flies under S); exp half1 + l-update hidden
// under PV k0 (P cols 16-31 only needed by k1); one wait fewer per tile;
// trailing barrier removed (top barrier of t+1 protects V/P overwrite).
// ---------------------------------------------------------------------------
#define SXSTR 528
#define SXH 0
#define SXL (SXH + 128 * SXSTR)
#define SBH (SXL + 128 * SXSTR)
#define SBL (SBH + 32 * SXSTR)
#define SVH (SBL + 32 * SXSTR)
#define SVL (SVH + 32 * SXSTR)
#define SPH (SVL + 32 * SXSTR)
#define SSC (SPH + 128 * 80)
#define SMK (SSC + 512)
#define SMTOT (SMK + 128)
#define NT (LYY / 32)

__global__ __launch_bounds__(256, 1)
void attn_mma_kernel(const int* __restrict__ mask, float* __restrict__ out)
{
    extern __shared__ char smc[];
    const uint32_t sa = smem_u32(smc);
    const int tid  = threadIdx.x;
    const int w    = tid >> 5;
    const int lane = tid & 31;
    const int lr   = lane >> 2;
    const int tig  = lane & 3;
    const int b    = blockIdx.y;
    const int x0   = blockIdx.x * 128;
    const int rw   = w * 16;

    const int* mB = mask + (size_t)b * LYY;
    const size_t gyB = (size_t)(b * LYY) * DD;
    const int pr = tid >> 3, pcb = tid & 7;

    auto issueYp = [&](int t) {
        size_t gro = gyB + (size_t)(t * 32 + pr) * DD;
        uint32_t o = sa + (uint32_t)(pr * SXSTR);
#pragma unroll
        for (int i = 0; i < 4; i++) {
            int c = pcb + 8 * i;
            cpa16(o + SBH + c * 16, g_yp_h + gro + c * 8);
            cpa16(o + SBL + c * 16, g_yp_l + gro + c * 8);
        }
        if (tid < 32) cpa4(sa + SMK + tid * 4, mB + t * 32 + tid);
    };
    auto issueYv = [&](int t) {
        size_t gro = gyB + (size_t)(t * 32 + pr) * DD;
        uint32_t o = sa + (uint32_t)(pr * SXSTR);
#pragma unroll
        for (int i = 0; i < 4; i++) {
            int c = pcb + 8 * i;
            cpa16(o + SVH + c * 16, g_yv_h + gro + c * 8);
            cpa16(o + SVL + c * 16, g_yv_l + gro + c * 8);
        }
    };

    // prologue: X tile (group 0), Yp(0) (group 1). yV(0) issued in-loop.
    {
        int r = tid >> 1;
        const __nv_bfloat16* srch = g_xp_h + (size_t)(b * LXX + x0 + r) * DD;
        const __nv_bfloat16* srcl = g_xp_l + (size_t)(b * LXX + x0 + r) * DD;
        uint32_t dh = sa + SXH + r * SXSTR;
        uint32_t dl = sa + SXL + r * SXSTR;
#pragma unroll
        for (int i = 0; i < 16; i++) {
            int c = (tid & 1) + 2 * i;
            cpa16(dh + c * 16, srch + c * 8);
            cpa16(dl + c * 16, srcl + c * 8);
        }
    }
    CP_COMMIT();
    issueYp(0);
    CP_COMMIT();

    const int* smk = (const int*)(smc + SMK);
    float* sSC = (float*)(smc + SSC);

    float O[32][4];
#pragma unroll
    for (int i = 0; i < 32; i++) { O[i][0] = O[i][1] = O[i][2] = O[i][3] = 0.f; }
    float m0 = -1e30f, m1 = -1e30f, l0 = 0.f, l1 = 0.f;

    const uint32_t aA  = sa + SXH + (rw + (lane & 7) + ((lane >> 3) & 1) * 8) * SXSTR
                       + (lane >> 4) * 16;
    const uint32_t aAl = aA + (uint32_t)(SXL - SXH);
    const uint32_t aB  = sa + SBH + ((lane & 7) + ((lane < 16) ? 0 : 8)) * SXSTR
                       + ((lane >> 3) & 1) * 16;
    const uint32_t aBl = aB + (uint32_t)(SBL - SBH);
    const uint32_t aP  = sa + SPH + ((lane & 7) + ((lane >> 3) & 1) * 8) * 80
                       + (lane >> 4) * 16;
    const uint32_t aVd = sa + SVH + ((lane & 7) + ((lane >> 3) & 1) * 8) * SXSTR
                       + w * 64 + ((lane < 16) ? 0 : 16);
    const uint32_t aVdl = aVd + (uint32_t)(SVL - SVH);

    const int r0 = rw + lr, r1 = rw + lr + 8;

#pragma unroll 1
    for (int t = 0; t < NT; t++) {
        // top: Yp(t) (+X at t=0) is the only pending group
        CP_WAIT0();
        __syncthreads();                 // Yp visible; PV(t-1) done by all
        issueYv(t);                      // flies under S
        CP_COMMIT();

        float sf[4][4];
#pragma unroll
        for (int nt = 0; nt < 4; nt++)
#pragma unroll
            for (int i = 0; i < 4; i++) sf[nt][i] = 0.f;

        // ---- S: register double-buffered frags ----
        uint32_t fa[2][8], fb[2][16];
        ldsm4(&fa[0][0], aA);
        ldsm4(&fa[0][4], aAl);
        ldsm4(&fb[0][0], aB);
        ldsm4(&fb[0][4], aBl);
        ldsm4(&fb[0][8], aB + 16 * SXSTR);
        ldsm4(&fb[0][12], aBl + 16 * SXSTR);
#pragma unroll
        for (int kk = 0; kk < 16; kk++) {
            const int cur = kk & 1, nxt = cur ^ 1;
            if (kk < 15) {
                const uint32_t ko = (uint32_t)((kk + 1) * 32);
                ldsm4(&fa[nxt][0], aA  + ko);
                ldsm4(&fa[nxt][4], aAl + ko);
                ldsm4(&fb[nxt][0], aB  + ko);
                ldsm4(&fb[nxt][4], aBl + ko);
                ldsm4(&fb[nxt][8], aB  + 16 * SXSTR + ko);
                ldsm4(&fb[nxt][12], aBl + 16 * SXSTR + ko);
            }
            const uint32_t* ah = &fa[cur][0];
            const uint32_t* al = &fa[cur][4];
            const uint32_t* bh = &fb[cur][0];
            const uint32_t* bl = &fb[cur][4];
            const uint32_t* ch = &fb[cur][8];
            const uint32_t* cl = &fb[cur][12];
            mma16816(sf[0], ah, bh[0], bh[1]);
            mma16816(sf[0], ah, bl[0], bl[1]);
            mma16816(sf[0], al, bh[0], bh[1]);
            mma16816(sf[1], ah, bh[2], bh[3]);
            mma16816(sf[1], ah, bl[2], bl[3]);
            mma16816(sf[1], al, bh[2], bh[3]);
            mma16816(sf[2], ah, ch[0], ch[1]);
            mma16816(sf[2], ah, cl[0], cl[1]);
            mma16816(sf[2], al, ch[0], ch[1]);
            mma16816(sf[3], ah, ch[2], ch[3]);
            mma16816(sf[3], ah, cl[2], cl[3]);
            mma16816(sf[3], al, ch[2], ch[3]);
        }

        // ---- mask + row max + scale ----
        float mx0 = -1e30f, mx1 = -1e30f;
#pragma unroll
        for (int nt = 0; nt < 4; nt++) {
            int j = 8 * nt + 2 * tig;
            if (smk[j])     { sf[nt][0] = -1e30f; sf[nt][2] = -1e30f; }
            if (smk[j + 1]) { sf[nt][1] = -1e30f; sf[nt][3] = -1e30f; }
            mx0 = fmaxf(mx0, fmaxf(sf[nt][0], sf[nt][1]));
            mx1 = fmaxf(mx1, fmaxf(sf[nt][2], sf[nt][3]));
        }
        mx0 = fmaxf(mx0, __shfl_xor_sync(0xffffffffu, mx0, 1));
        mx0 = fmaxf(mx0, __shfl_xor_sync(0xffffffffu, mx0, 2));
        mx1 = fmaxf(mx1, __shfl_xor_sync(0xffffffffu, mx1, 1));
        mx1 = fmaxf(mx1, __shfl_xor_sync(0xffffffffu, mx1, 2));

        float mn0 = fmaxf(m0, mx0), mn1 = fmaxf(m1, mx1);
        float sc0 = ex2a((m0 - mn0) * L2E);
        float sc1 = ex2a((m1 - mn1) * L2E);
        m0 = mn0; m1 = mn1;
        const float mnL0 = mn0 * L2E, mnL1 = mn1 * L2E;
        if (tig == 0) { sSC[r0] = sc0; sSC[r1] = sc1; }

        // ---- exp HALF0 (S cols 0-15, used by PV k=0) + write P half0 ----
        uint32_t ph[8];
        float rs0 = 0.f, rs1 = 0.f;
#pragma unroll
        for (int nt = 0; nt < 2; nt++) {
            float p00 = ex2a(fmaf(sf[nt][0], L2E, -mnL0));
            float p01 = ex2a(fmaf(sf[nt][1], L2E, -mnL0));
            float p10 = ex2a(fmaf(sf[nt][2], L2E, -mnL1));
            float p11 = ex2a(fmaf(sf[nt][3], L2E, -mnL1));
            uint32_t h0 = cvt2bf(p00, p01);
            uint32_t h1 = cvt2bf(p10, p11);
            ph[nt * 2]     = h0;
            ph[nt * 2 + 1] = h1;
            rs0 += __uint_as_float(h0 << 16) + __uint_as_float(h0 & 0xffff0000u);
            rs1 += __uint_as_float(h1 << 16) + __uint_as_float(h1 & 0xffff0000u);
            *(uint32_t*)(smc + SPH + r0 * 80 + 16 * nt + 4 * tig) = h0;
            *(uint32_t*)(smc + SPH + r1 * 80 + 16 * nt + 4 * tig) = h1;
        }

        // mid barrier: P0 visible, yV(t) visible, all S reads done
        CP_WAIT0();
        __syncthreads();

        if (t < NT - 1) issueYp(t + 1);   // flies under PV
        CP_COMMIT();

        // ---- PV k=0: V frags + P0 frags; exp half1 hides under the mma ----
        {
            uint32_t vh0[4], vl0[4], vh1[4], vl1[4];
            ldsm4t(vh0, aVd);
            ldsm4t(vh1, aVd + 32);
            ldsm4t(vl0, aVdl);
            ldsm4t(vl1, aVdl + 32);
            uint32_t pa[2][4];
            ldsm4(pa[0], aP);

            // exp HALF1 (independent of the k0 mma stream below)
#pragma unroll
            for (int nt = 2; nt < 4; nt++) {
                float p00 = ex2a(fmaf(sf[nt][0], L2E, -mnL0));
                float p01 = ex2a(fmaf(sf[nt][1], L2E, -mnL0));
                float p10 = ex2a(fmaf(sf[nt][2], L2E, -mnL1));
                float p11 = ex2a(fmaf(sf[nt][3], L2E, -mnL1));
                uint32_t h0 = cvt2bf(p00, p01);
                uint32_t h1 = cvt2bf(p10, p11);
                ph[nt * 2]     = h0;
                ph[nt * 2 + 1] = h1;
                rs0 += __uint_as_float(h0 << 16) + __uint_as_float(h0 & 0xffff0000u);
                rs1 += __uint_as_float(h1 << 16) + __uint_as_float(h1 & 0xffff0000u);
                *(uint32_t*)(smc + SPH + r0 * 80 + 16 * nt + 4 * tig) = h0;
                *(uint32_t*)(smc + SPH + r1 * 80 + 16 * nt + 4 * tig) = h1;
            }
            rs0 += __shfl_xor_sync(0xffffffffu, rs0, 1);
            rs0 += __shfl_xor_sync(0xffffffffu, rs0, 2);
            rs1 += __shfl_xor_sync(0xffffffffu, rs1, 1);
            rs1 += __shfl_xor_sync(0xffffffffu, rs1, 2);
            l0 = l0 * sc0 + rs0;
            l1 = l1 * sc1 + rs1;

#pragma unroll
            for (int mg = 0; mg < 8; mg++) {
                const int cur = mg & 1, nxt = cur ^ 1;
                if (mg < 7) ldsm4(pa[nxt], aP + (mg + 1) * 1280);
                {
                    float sA = sSC[mg * 16 + lr];
                    float sB = sSC[mg * 16 + lr + 8];
#pragma unroll
                    for (int df = 0; df < 4; df++) {
                        O[mg * 4 + df][0] *= sA; O[mg * 4 + df][1] *= sA;
                        O[mg * 4 + df][2] *= sB; O[mg * 4 + df][3] *= sB;
                    }
                }
                const uint32_t* pA = pa[cur];
                mma16816(O[mg * 4 + 0], pA, vh0[0], vh0[1]);
                mma16816(O[mg * 4 + 0], pA, vl0[0], vl0[1]);
                mma16816(O[mg * 4 + 1], pA, vh0[2], vh0[3]);
                mma16816(O[mg * 4 + 1], pA, vl0[2], vl0[3]);
                mma16816(O[mg * 4 + 2], pA, vh1[0], vh1[1]);
                mma16816(O[mg * 4 + 2], pA, vl1[0], vl1[1]);
                mma16816(O[mg * 4 + 3], pA, vh1[2], vh1[3]);
                mma16816(O[mg * 4 + 3], pA, vl1[2], vl1[3]);
            }
        }
        __syncthreads();                  // P half1 visible

        // ---- PV k=1 ----
        {
            uint32_t vh0[4], vl0[4], vh1[4], vl1[4];
            ldsm4t(vh0, aVd  + 16 * SXSTR);
            ldsm4t(vh1, aVd  + 16 * SXSTR + 32);
            ldsm4t(vl0, aVdl + 16 * SXSTR);
            ldsm4t(vl1, aVdl + 16 * SXSTR + 32);
            uint32_t pa[2][4];
            ldsm4(pa[0], aP + 32);
#pragma unroll
            for (int mg = 0; mg < 8; mg++) {
                const int cur = mg & 1, nxt = cur ^ 1;
                if (mg < 7) ldsm4(pa[nxt], aP + (mg + 1) * 1280 + 32);
                const uint32_t* pA = pa[cur];
                mma16816(O[mg * 4 + 0], pA, vh0[0], vh0[1]);
                mma16816(O[mg * 4 + 0], pA, vl0[0], vl0[1]);
                mma16816(O[mg * 4 + 1], pA, vh0[2], vh0[3]);
                mma16816(O[mg * 4 + 1], pA, vl0[2], vl0[3]);
                mma16816(O[mg * 4 + 2], pA, vh1[0], vh1[1]);
                mma16816(O[mg * 4 + 2], pA, vl1[0], vl1[1]);
                mma16816(O[mg * 4 + 3], pA, vh1[2], vh1[3]);
                mma16816(O[mg * 4 + 3], pA, vl1[2], vl1[3]);
            }
        }
        // no trailing barrier: top barrier of t+1 protects V/P/sSC overwrite
    }

    if (tig == 0) { sSC[r0] = 1.0f / l0; sSC[r1] = 1.0f / l1; }
    __syncthreads();
#pragma unroll
    for (int mg = 0; mg < 8; mg++) {
        float iA = sSC[mg * 16 + lr];
        float iB = sSC[mg * 16 + lr + 8];
        float* oA = out + (size_t)(b * LXX + x0 + mg * 16 + lr) * DD + w * 32;
        float* oB = oA + 8 * DD;
#pragma unroll
        for (int df = 0; df < 4; df++) {
            int c = df * 8 + tig * 2;
            *(float2*)(oA + c) = make_float2(O[mg * 4 + df][0] * iA,
                                             O[mg * 4 + df][1] * iA);
            *(float2*)(oB + c) = make_float2(O[mg * 4 + df][2] * iB,
                                             O[mg * 4 + df][3] * iB);
        }
    }
}

// ---------------------------------------------------------------------------
extern "C" void kernel_launch(void* const* d_in, const int* in_sizes, int n_in,
                              void* d_out, int out_size)
{
    const float* x    = (const float*)d_in[0];
    const float* y    = (const float*)d_in[1];
    const int* mask   = (const int*)d_in[2];
    const float* W    = (const float*)d_in[3];
    const float* bias = (const float*)d_in[4];
    float* out        = (float*)d_out;

    split_all<<<SPLIT_WBLK + 2 * SPLIT_HALF, 256>>>(x, y, W);

    cudaFuncSetAttribute(proj_mma_kernel,
                         cudaFuncAttributeMaxDynamicSharedMemorySize, PJ_TOT);
    proj_mma_kernel<<<dim3((BB * (LXX + LYY)) / 128, 2), 256, PJ_TOT>>>(bias);

    cudaFuncSetAttribute(attn_mma_kernel,
                         cudaFuncAttributeMaxDynamicSharedMemorySize, SMTOT);
    attn_mma_kernel<<<dim3(LXX / 128, BB), 256, SMTOT>>>(mask, out);
}

// round 16
// speedup vs baseline: 1.0606x; 1.0606x over previous
#include <cuda_runtime.h>
#include <cuda_bf16.h>
#include <cstdint>

#define BB 8
#define LXX 2048
#define LYY 2048
#define DD 256

// ---------------- global scratch (no cudaMalloc allowed) ----------------
__device__ __nv_bfloat16 g_x_h[BB * LXX * DD];    // raw x, bf16 hi/lo
__device__ __nv_bfloat16 g_x_l[BB * LXX * DD];
__device__ __nv_bfloat16 g_xp_h[BB * LXX * DD];
__device__ __nv_bfloat16 g_xp_l[BB * LXX * DD];
__device__ __nv_bfloat16 g_yp_h[BB * LYY * DD];
__device__ __nv_bfloat16 g_yp_l[BB * LYY * DD];
__device__ __nv_bfloat16 g_yv_h[BB * LYY * DD];   // raw y, bf16 hi/lo
__device__ __nv_bfloat16 g_yv_l[BB * LYY * DD];
__device__ __nv_bfloat16 g_W_h[DD * DD];
__device__ __nv_bfloat16 g_W_l[DD * DD];

// ---------------- helpers (portable PTX only: sm_80-era) ----------------
__device__ __forceinline__ uint32_t smem_u32(const void* p) {
    uint32_t a;
    asm("{ .reg .u64 t; cvta.to.shared.u64 t, %1; cvt.u32.u64 %0, t; }" : "=r"(a) : "l"(p));
    return a;
}
__device__ __forceinline__ void cpa16(uint32_t s, const void* g) {
    asm volatile("cp.async.cg.shared.global [%0], [%1], 16;" :: "r"(s), "l"(g));
}
__device__ __forceinline__ void cpa4(uint32_t s, const void* g) {
    asm volatile("cp.async.ca.shared.global [%0], [%1], 4;" :: "r"(s), "l"(g));
}
#define CP_COMMIT() asm volatile("cp.async.commit_group;" ::: "memory")
#define CP_WAIT0()  asm volatile("cp.async.wait_group 0;" ::: "memory")
#define CP_WAIT1()  asm volatile("cp.async.wait_group 1;" ::: "memory")

__device__ __forceinline__ void ldsm4(uint32_t r[4], uint32_t a) {
    asm volatile("ldmatrix.sync.aligned.m8n8.x4.shared.b16 {%0,%1,%2,%3}, [%4];"
                 : "=r"(r[0]), "=r"(r[1]), "=r"(r[2]), "=r"(r[3]) : "r"(a));
}
__device__ __forceinline__ void ldsm4t(uint32_t r[4], uint32_t a) {
    asm volatile("ldmatrix.sync.aligned.m8n8.x4.trans.shared.b16 {%0,%1,%2,%3}, [%4];"
                 : "=r"(r[0]), "=r"(r[1]), "=r"(r[2]), "=r"(r[3]) : "r"(a));
}
__device__ __forceinline__ void mma16816(float c[4], const uint32_t a[4],
                                         uint32_t b0, uint32_t b1) {
    asm volatile(
        "mma.sync.aligned.m16n8k16.row.col.f32.bf16.bf16.f32 "
        "{%0,%1,%2,%3}, {%4,%5,%6,%7}, {%8,%9}, {%0,%1,%2,%3};"
        : "+f"(c[0]), "+f"(c[1]), "+f"(c[2]), "+f"(c[3])
        : "r"(a[0]), "r"(a[1]), "r"(a[2]), "r"(a[3]), "r"(b0), "r"(b1));
}
__device__ __forceinline__ uint32_t cvt2bf(float lo, float hi) {
    uint32_t r;
    asm("cvt.rn.bf16x2.f32 %0, %1, %2;" : "=r"(r) : "f"(hi), "f"(lo));
    return r;
}
// MUFU exp2 (ex2.approx): ~2 ulp, returns 0 for very negative inputs.
__device__ __forceinline__ float ex2a(float x) {
    float r;
    asm("ex2.approx.f32 %0, %1;" : "=f"(r) : "f"(x));
    return r;
}
#define L2E 1.4426950408889634f

// ---------------------------------------------------------------------------
// Fused elementwise bf16 hi/lo splitter: blocks [0,64) -> W, [64,4160) -> x,
// [4160,8256) -> y.
// ---------------------------------------------------------------------------
#define SPLIT_WBLK ((DD * DD) / 1024)              // 64
#define SPLIT_HALF ((BB * LXX * DD) / 1024)        // 4096
__global__ __launch_bounds__(256)
void split_all(const float* __restrict__ x, const float* __restrict__ y,
               const float* __restrict__ W)
{
    const int bidx = blockIdx.x;
    const float* src;
    __nv_bfloat16 *dh, *dl;
    size_t i;
    if (bidx < SPLIT_WBLK) {
        src = W; dh = g_W_h; dl = g_W_l;
        i = ((size_t)bidx * 256 + threadIdx.x) * 4;
    } else if (bidx < SPLIT_WBLK + SPLIT_HALF) {
        src = x; dh = g_x_h; dl = g_x_l;
        i = ((size_t)(bidx - SPLIT_WBLK) * 256 + threadIdx.x) * 4;
    } else {
        src = y; dh = g_yv_h; dl = g_yv_l;
        i = ((size_t)(bidx - SPLIT_WBLK - SPLIT_HALF) * 256 + threadIdx.x) * 4;
    }
    float4 v = *(const float4*)(src + i);
    float vv[4] = {v.x, v.y, v.z, v.w};
    __nv_bfloat16 h[4], l[4];
#pragma unroll
    for (int k = 0; k < 4; k++) {
        h[k] = __float2bfloat16_rn(vv[k]);
        l[k] = __float2bfloat16_rn(vv[k] - __bfloat162float(h[k]));
    }
    *(uint2*)&dh[i] = *(uint2*)h;
    *(uint2*)&dl[i] = *(uint2*)l;
}

// ---------------------------------------------------------------------------
// Tensor-core projection v3: C = relu(A @ W^T + b) -> bf16 h/l splits.
// CTA = 128x128; A and W streamed per k32 chunk, double-buffered, 2 CTAs/SM.
// NEW: ONE barrier per chunk (wait0 -> sync -> prefetch-into-freed-stage ->
// compute). The single barrier proves both stage arrival consumption safety
// and that the stage being overwritten has been fully read.
// ---------------------------------------------------------------------------
#define PJ_AH 0
#define PJ_AL 10240
#define PJ_WH 20480
#define PJ_WL 30720
#define PJ_STG 40960
#define PJ_TOT (2 * PJ_STG)

__global__ __launch_bounds__(256, 2)
void proj_mma_kernel(const float* __restrict__ bias)
{
    extern __shared__ char smc[];
    const uint32_t sa = smem_u32(smc);
    const int tid  = threadIdx.x;
    const int w    = tid >> 5;
    const int lane = tid & 31;
    const int lr   = lane >> 2;
    const int tig  = lane & 3;
    const int rw   = w * 16;
    const int wcol0 = blockIdx.y * 128;
    const int row0  = blockIdx.x * 128;
    const bool isx  = row0 < BB * LXX;
    const int arow0 = isx ? row0 : row0 - BB * LXX;

    const __nv_bfloat16* __restrict__ Ah = isx ? g_x_h : g_yv_h;
    const __nv_bfloat16* __restrict__ Al = isx ? g_x_l : g_yv_l;
    __nv_bfloat16* __restrict__ Ch = isx ? g_xp_h : g_yp_h;
    __nv_bfloat16* __restrict__ Cl = isx ? g_xp_l : g_yp_l;

    const int pre_r = tid >> 1, pre_hb = tid & 1;

    auto pref = [&](int s, int kc) {
        const uint32_t st = sa + (uint32_t)(s * PJ_STG + pre_r * 80 + pre_hb * 32);
        const size_t ao = (size_t)(arow0 + pre_r) * DD + kc * 32 + pre_hb * 16;
        const size_t wo = (size_t)(wcol0 + pre_r) * DD + kc * 32 + pre_hb * 16;
        cpa16(st + PJ_AH,      Ah + ao);  cpa16(st + PJ_AH + 16,  Ah + ao + 8);
        cpa16(st + PJ_AL,      Al + ao);  cpa16(st + PJ_AL + 16,  Al + ao + 8);
        cpa16(st + PJ_WH,      g_W_h + wo); cpa16(st + PJ_WH + 16, g_W_h + wo + 8);
        cpa16(st + PJ_WL,      g_W_l + wo); cpa16(st + PJ_WL + 16, g_W_l + wo + 8);
    };
    pref(0, 0);
    CP_COMMIT();

    float O[16][4];
#pragma unroll
    for (int i = 0; i < 16; i++) { O[i][0] = O[i][1] = O[i][2] = O[i][3] = 0.f; }

    const uint32_t aAo = (uint32_t)(PJ_AH + (rw + (lane & 7) + ((lane >> 3) & 1) * 8) * 80
                        + (lane >> 4) * 16);
    const uint32_t aWo = (uint32_t)(PJ_WH + ((lane & 7) + ((lane < 16) ? 0 : 8)) * 80
                        + ((lane >> 3) & 1) * 16);

#pragma unroll 1
    for (int kc = 0; kc < 8; kc++) {
        const int s = kc & 1;
        CP_WAIT0();          // stage s for chunk kc arrived
        __syncthreads();     // all warps done reading stage s^1 (chunk kc-1)
        if (kc < 7) { pref(s ^ 1, kc + 1); CP_COMMIT(); }

        const uint32_t stb = sa + (uint32_t)(s * PJ_STG);
        const uint32_t aA  = stb + aAo;
        const uint32_t aAl = aA + (PJ_AL - PJ_AH);
        const uint32_t aW  = stb + aWo;
        const uint32_t aWl = aW + (PJ_WL - PJ_WH);
#pragma unroll
        for (int kk = 0; kk < 2; kk++) {
            uint32_t ah[4], al[4];
            ldsm4(ah, aA  + kk * 32);
            ldsm4(al, aAl + kk * 32);
            uint32_t wb[2][8];
            ldsm4(&wb[0][0], aW  + kk * 32);
            ldsm4(&wb[0][4], aWl + kk * 32);
#pragma unroll
            for (int g = 0; g < 8; g++) {
                const int cur = g & 1, nxt = cur ^ 1;
                if (g < 7) {
                    ldsm4(&wb[nxt][0], aW  + (g + 1) * 1280 + kk * 32);
                    ldsm4(&wb[nxt][4], aWl + (g + 1) * 1280 + kk * 32);
                }
                const uint32_t* bh = &wb[cur][0];
                const uint32_t* bl = &wb[cur][4];
                mma16816(O[2 * g],     ah, bh[0], bh[1]);
                mma16816(O[2 * g],     ah, bl[0], bl[1]);
                mma16816(O[2 * g],     al, bh[0], bh[1]);
                mma16816(O[2 * g + 1], ah, bh[2], bh[3]);
                mma16816(O[2 * g + 1], ah, bl[2], bl[3]);
                mma16816(O[2 * g + 1], al, bh[2], bh[3]);
            }
        }
    }

    // ---- epilogue: bias + relu + h/l split + store ----
    const int r0g = arow0 + rw + lr;
#pragma unroll
    for (int f = 0; f < 16; f++) {
        int c = wcol0 + f * 8 + tig * 2;
        float b0 = __ldg(bias + c), b1 = __ldg(bias + c + 1);
        {
            float v0 = fmaxf(O[f][0] + b0, 0.f), v1 = fmaxf(O[f][1] + b1, 0.f);
            uint32_t h = cvt2bf(v0, v1);
            float q0 = v0 - __uint_as_float(h << 16);
            float q1 = v1 - __uint_as_float(h & 0xffff0000u);
            uint32_t l = cvt2bf(q0, q1);
            size_t o = (size_t)r0g * DD + c;
            *(uint32_t*)&Ch[o] = h;
            *(uint32_t*)&Cl[o] = l;
        }
        {
            float v0 = fmaxf(O[f][2] + b0, 0.f), v1 = fmaxf(O[f][3] + b1, 0.f);
            uint32_t h = cvt2bf(v0, v1);
            float q0 = v0 - __uint_as_float(h << 16);
            float q1 = v1 - __uint_as_float(h & 0xffff0000u);
            uint32_t l = cvt2bf(q0, q1);
            size_t o = (size_t)(r0g + 8) * DD + c;
            *(uint32_t*)&Ch[o] = h;
            *(uint32_t*)&Cl[o] = l;
        }
    }
}

// ---------------------------------------------------------------------------
// Fused mma.sync attention (R14 verbatim): 256 threads, XTILE 128, JTILE 32.
// S phase: 3-pass hh+hl+lh, register double-buffered frags. MUFU softmax.
// PV: d-split + P-frag prefetch; O-rescale folded in at k==0. Single
// mid-tile barrier covers P visibility + yV visibility + S-reads-done.
// ---------------------------------------------------------------------------
#define SXSTR 528
#define SXH 0
#define SXL (SXH + 128 * SXSTR)
#define SBH (SXL + 128 * SXSTR)
#define SBL (SBH + 32 * SXSTR)
#define SVH (SBL + 32 * SXSTR)
#define SVL (SVH + 32 * SXSTR)
#define SPH (SVL + 32 * SXSTR)
#define SSC (SPH + 128 * 80)
#define SMK (SSC + 512)
#define SMTOT (SMK + 128)
#define NT (LYY / 32)

__global__ __launch_bounds__(256, 1)
void attn_mma_kernel(const int* __restrict__ mask, float* __restrict__ out)
{
    extern __shared__ char smc[];
    const uint32_t sa = smem_u32(smc);
    const int tid  = threadIdx.x;
    const int w    = tid >> 5;
    const int lane = tid & 31;
    const int lr   = lane >> 2;
    const int tig  = lane & 3;
    const int b    = blockIdx.y;
    const int x0   = blockIdx.x * 128;
    const int rw   = w * 16;

    const int* mB = mask + (size_t)b * LYY;
    const size_t gyB = (size_t)(b * LYY) * DD;
    const int pr = tid >> 3, pcb = tid & 7;

    auto issueYp = [&](int t) {
        size_t gro = gyB + (size_t)(t * 32 + pr) * DD;
        uint32_t o = sa + (uint32_t)(pr * SXSTR);
#pragma unroll
        for (int i = 0; i < 4; i++) {
            int c = pcb + 8 * i;
            cpa16(o + SBH + c * 16, g_yp_h + gro + c * 8);
            cpa16(o + SBL + c * 16, g_yp_l + gro + c * 8);
        }
        if (tid < 32) cpa4(sa + SMK + tid * 4, mB + t * 32 + tid);
    };
    auto issueYv = [&](int t) {
        size_t gro = gyB + (size_t)(t * 32 + pr) * DD;
        uint32_t o = sa + (uint32_t)(pr * SXSTR);
#pragma unroll
        for (int i = 0; i < 4; i++) {
            int c = pcb + 8 * i;
            cpa16(o + SVH + c * 16, g_yv_h + gro + c * 8);
            cpa16(o + SVL + c * 16, g_yv_l + gro + c * 8);
        }
    };

    {
        int r = tid >> 1;
        const __nv_bfloat16* srch = g_xp_h + (size_t)(b * LXX + x0 + r) * DD;
        const __nv_bfloat16* srcl = g_xp_l + (size_t)(b * LXX + x0 + r) * DD;
        uint32_t dh = sa + SXH + r * SXSTR;
        uint32_t dl = sa + SXL + r * SXSTR;
#pragma unroll
        for (int i = 0; i < 16; i++) {
            int c = (tid & 1) + 2 * i;
            cpa16(dh + c * 16, srch + c * 8);
            cpa16(dl + c * 16, srcl + c * 8);
        }
    }
    CP_COMMIT();
    issueYp(0);
    CP_COMMIT();
    issueYv(0);
    CP_COMMIT();

    const int* smk = (const int*)(smc + SMK);
    float* sSC = (float*)(smc + SSC);

    float O[32][4];
#pragma unroll
    for (int i = 0; i < 32; i++) { O[i][0] = O[i][1] = O[i][2] = O[i][3] = 0.f; }
    float m0 = -1e30f, m1 = -1e30f, l0 = 0.f, l1 = 0.f;

    const uint32_t aA  = sa + SXH + (rw + (lane & 7) + ((lane >> 3) & 1) * 8) * SXSTR
                       + (lane >> 4) * 16;
    const uint32_t aAl = aA + (uint32_t)(SXL - SXH);
    const uint32_t aB  = sa + SBH + ((lane & 7) + ((lane < 16) ? 0 : 8)) * SXSTR
                       + ((lane >> 3) & 1) * 16;
    const uint32_t aBl = aB + (uint32_t)(SBL - SBH);
    const uint32_t aP  = sa + SPH + ((lane & 7) + ((lane >> 3) & 1) * 8) * 80
                       + (lane >> 4) * 16;
    const uint32_t aVd = sa + SVH + ((lane & 7) + ((lane >> 3) & 1) * 8) * SXSTR
                       + w * 64 + ((lane < 16) ? 0 : 16);
    const uint32_t aVdl = aVd + (uint32_t)(SVL - SVH);

    const int r0 = rw + lr, r1 = rw + lr + 8;

#pragma unroll 1
    for (int t = 0; t < NT; t++) {
        CP_WAIT1();                    // Yp(t) (+X at t=0) arrived
        __syncthreads();

        float sf[4][4];
#pragma unroll
        for (int nt = 0; nt < 4; nt++)
#pragma unroll
            for (int i = 0; i < 4; i++) sf[nt][i] = 0.f;

        // ---- S: register double-buffered frags ----
        uint32_t fa[2][8], fb[2][16];
        ldsm4(&fa[0][0], aA);
        ldsm4(&fa[0][4], aAl);
        ldsm4(&fb[0][0], aB);
        ldsm4(&fb[0][4], aBl);
        ldsm4(&fb[0][8], aB + 16 * SXSTR);
        ldsm4(&fb[0][12], aBl + 16 * SXSTR);
#pragma unroll
        for (int kk = 0; kk < 16; kk++) {
            const int cur = kk & 1, nxt = cur ^ 1;
            if (kk < 15) {
                const uint32_t ko = (uint32_t)((kk + 1) * 32);
                ldsm4(&fa[nxt][0], aA  + ko);
                ldsm4(&fa[nxt][4], aAl + ko);
                ldsm4(&fb[nxt][0], aB  + ko);
                ldsm4(&fb[nxt][4], aBl + ko);
                ldsm4(&fb[nxt][8], aB  + 16 * SXSTR + ko);
                ldsm4(&fb[nxt][12], aBl + 16 * SXSTR + ko);
            }
            const uint32_t* ah = &fa[cur][0];
            const uint32_t* al = &fa[cur][4];
            const uint32_t* bh = &fb[cur][0];
            const uint32_t* bl = &fb[cur][4];
            const uint32_t* ch = &fb[cur][8];
            const uint32_t* cl = &fb[cur][12];
            mma16816(sf[0], ah, bh[0], bh[1]);
            mma16816(sf[0], ah, bl[0], bl[1]);
            mma16816(sf[0], al, bh[0], bh[1]);
            mma16816(sf[1], ah, bh[2], bh[3]);
            mma16816(sf[1], ah, bl[2], bl[3]);
            mma16816(sf[1], al, bh[2], bh[3]);
            mma16816(sf[2], ah, ch[0], ch[1]);
            mma16816(sf[2], ah, cl[0], cl[1]);
            mma16816(sf[2], al, ch[0], ch[1]);
            mma16816(sf[3], ah, ch[2], ch[3]);
            mma16816(sf[3], ah, cl[2], cl[3]);
            mma16816(sf[3], al, ch[2], ch[3]);
        }

        // ---- mask + online softmax (MUFU exp) ----
        float mx0 = -1e30f, mx1 = -1e30f;
#pragma unroll
        for (int nt = 0; nt < 4; nt++) {
            int j = 8 * nt + 2 * tig;
            if (smk[j])     { sf[nt][0] = -1e30f; sf[nt][2] = -1e30f; }
            if (smk[j + 1]) { sf[nt][1] = -1e30f; sf[nt][3] = -1e30f; }
            mx0 = fmaxf(mx0, fmaxf(sf[nt][0], sf[nt][1]));
            mx1 = fmaxf(mx1, fmaxf(sf[nt][2], sf[nt][3]));
        }
        mx0 = fmaxf(mx0, __shfl_xor_sync(0xffffffffu, mx0, 1));
        mx0 = fmaxf(mx0, __shfl_xor_sync(0xffffffffu, mx0, 2));
        mx1 = fmaxf(mx1, __shfl_xor_sync(0xffffffffu, mx1, 1));
        mx1 = fmaxf(mx1, __shfl_xor_sync(0xffffffffu, mx1, 2));

        float mn0 = fmaxf(m0, mx0), mn1 = fmaxf(m1, mx1);
        float sc0 = ex2a((m0 - mn0) * L2E);
        float sc1 = ex2a((m1 - mn1) * L2E);
        m0 = mn0; m1 = mn1;
        const float mnL0 = mn0 * L2E, mnL1 = mn1 * L2E;

        uint32_t ph[8];
        float rs0 = 0.f, rs1 = 0.f;
#pragma unroll
        for (int nt = 0; nt < 4; nt++) {
            float p00 = ex2a(fmaf(sf[nt][0], L2E, -mnL0));
            float p01 = ex2a(fmaf(sf[nt][1], L2E, -mnL0));
            float p10 = ex2a(fmaf(sf[nt][2], L2E, -mnL1));
            float p11 = ex2a(fmaf(sf[nt][3], L2E, -mnL1));
            uint32_t h0 = cvt2bf(p00, p01);
            uint32_t h1 = cvt2bf(p10, p11);
            ph[nt * 2]     = h0;
            ph[nt * 2 + 1] = h1;
            rs0 += __uint_as_float(h0 << 16) + __uint_as_float(h0 & 0xffff0000u);
            rs1 += __uint_as_float(h1 << 16) + __uint_as_float(h1 & 0xffff0000u);
        }
        rs0 += __shfl_xor_sync(0xffffffffu, rs0, 1);
        rs0 += __shfl_xor_sync(0xffffffffu, rs0, 2);
        rs1 += __shfl_xor_sync(0xffffffffu, rs1, 1);
        rs1 += __shfl_xor_sync(0xffffffffu, rs1, 2);
        l0 = l0 * sc0 + rs0;
        l1 = l1 * sc1 + rs1;

        // write P-hi + per-row scale
#pragma unroll
        for (int nt = 0; nt < 4; nt++) {
            *(uint32_t*)(smc + SPH + r0 * 80 + 16 * nt + 4 * tig) = ph[nt * 2];
            *(uint32_t*)(smc + SPH + r1 * 80 + 16 * nt + 4 * tig) = ph[nt * 2 + 1];
        }
        if (tig == 0) { sSC[r0] = sc0; sSC[r1] = sc1; }

        // single mid-tile barrier: P visible, yV(t) visible, all S reads done
        CP_WAIT0();
        __syncthreads();

        if (t < NT - 1) issueYp(t + 1);
        CP_COMMIT();

        // ---- PV: O += Ph @ (Vh + Vl); rescale folded in at k==0 ----
#pragma unroll
        for (int k = 0; k < 2; k++) {
            uint32_t vh0[4], vl0[4], vh1[4], vl1[4];
            ldsm4t(vh0, aVd  + k * 16 * SXSTR);
            ldsm4t(vh1, aVd  + k * 16 * SXSTR + 32);
            ldsm4t(vl0, aVdl + k * 16 * SXSTR);
            ldsm4t(vl1, aVdl + k * 16 * SXSTR + 32);
            uint32_t pa[2][4];
            ldsm4(pa[0], aP + k * 32);
#pragma unroll
            for (int mg = 0; mg < 8; mg++) {
                const int cur = mg & 1, nxt = cur ^ 1;
                if (mg < 7) ldsm4(pa[nxt], aP + (mg + 1) * 1280 + k * 32);
                if (k == 0) {
                    float sA = sSC[mg * 16 + lr];
                    float sB = sSC[mg * 16 + lr + 8];
#pragma unroll
                    for (int df = 0; df < 4; df++) {
                        O[mg * 4 + df][0] *= sA; O[mg * 4 + df][1] *= sA;
                        O[mg * 4 + df][2] *= sB; O[mg * 4 + df][3] *= sB;
                    }
                }
                const uint32_t* pA = pa[cur];
                mma16816(O[mg * 4 + 0], pA, vh0[0], vh0[1]);
                mma16816(O[mg * 4 + 0], pA, vl0[0], vl0[1]);
                mma16816(O[mg * 4 + 1], pA, vh0[2], vh0[3]);
                mma16816(O[mg * 4 + 1], pA, vl0[2], vl0[3]);
                mma16816(O[mg * 4 + 2], pA, vh1[0], vh1[1]);
                mma16816(O[mg * 4 + 2], pA, vl1[0], vl1[1]);
                mma16816(O[mg * 4 + 3], pA, vh1[2], vh1[3]);
                mma16816(O[mg * 4 + 3], pA, vl1[2], vl1[3]);
            }
        }
        __syncthreads();               // V + P reads done before overwrite

        if (t < NT - 1) issueYv(t + 1);
        CP_COMMIT();
    }

    if (tig == 0) { sSC[r0] = 1.0f / l0; sSC[r1] = 1.0f / l1; }
    __syncthreads();
#pragma unroll
    for (int mg = 0; mg < 8; mg++) {
        float iA = sSC[mg * 16 + lr];
        float iB = sSC[mg * 16 + lr + 8];
        float* oA = out + (size_t)(b * LXX + x0 + mg * 16 + lr) * DD + w * 32;
        float* oB = oA + 8 * DD;
#pragma unroll
        for (int df = 0; df < 4; df++) {
            int c = df * 8 + tig * 2;
            *(float2*)(oA + c) = make_float2(O[mg * 4 + df][0] * iA,
                                             O[mg * 4 + df][1] * iA);
            *(float2*)(oB + c) = make_float2(O[mg * 4 + df][2] * iB,
                                             O[mg * 4 + df][3] * iB);
        }
    }
}

// ---------------------------------------------------------------------------
extern "C" void kernel_launch(void* const* d_in, const int* in_sizes, int n_in,
                              void* d_out, int out_size)
{
    const float* x    = (const float*)d_in[0];
    const float* y    = (const float*)d_in[1];
    const int* mask   = (const int*)d_in[2];
    const float* W    = (const float*)d_in[3];
    const float* bias = (const float*)d_in[4];
    float* out        = (float*)d_out;

    split_all<<<SPLIT_WBLK + 2 * SPLIT_HALF, 256>>>(x, y, W);

    cudaFuncSetAttribute(proj_mma_kernel,
                         cudaFuncAttributeMaxDynamicSharedMemorySize, PJ_TOT);
    proj_mma_kernel<<<dim3((BB * (LXX + LYY)) / 128, 2), 256, PJ_TOT>>>(bias);

    cudaFuncSetAttribute(attn_mma_kernel,
                         cudaFuncAttributeMaxDynamicSharedMemorySize, SMTOT);
    attn_mma_kernel<<<dim3(LXX / 128, BB), 256, SMTOT>>>(mask, out);
}